// round 6
// baseline (speedup 1.0000x reference)
#include <cuda_runtime.h>
#include <cuda_bf16.h>
#include <cfloat>
#include <cstdint>

#define E_DIM   64
#define K_CODE  1024
#define MT      256           // tokens per block
#define NTILES  128           // 1024 codes / 8 per mma tile
#define TAU     2e-3f
#define NCAND   6

// Output layout (float32, tuple order)
#define OFF_ZQ   0
#define OFF_DIFF 4194304
#define OFF_IND  4194305
#define OFF_NEMB 4259841
#define OFF_NCS  4325377
#define OFF_NEA  4326401

// smem layout (word/byte offsets)
#define SM_B     0            // 1024 codes x 36 words (bf16(2w) padded)  147456 B
#define SM_X     147456       // 256 x 68 fp32                             69632 B
#define SM_WN    217088       // 1024 fp32                                  4096 B
#define SM_FIN   221184       // 256 int                                    1024 B
#define SM_DSUM  222208       // 8 fp32                                       32 B
#define SM_TOTAL 222240

__device__ float         g_wnorm[K_CODE];
__device__ double        g_diff_acc;
__device__ __nv_bfloat16 g_Bbf16[K_CODE * E_DIM];   // bf16(2*w), k-contiguous

__device__ __forceinline__ void mma16816(float* c, const uint32_t* a,
                                         uint32_t b0, uint32_t b1) {
    asm volatile(
        "mma.sync.aligned.m16n8k16.row.col.f32.bf16.bf16.f32 "
        "{%0,%1,%2,%3}, {%4,%5,%6,%7}, {%8,%9}, {%0,%1,%2,%3};"
        : "+f"(c[0]), "+f"(c[1]), "+f"(c[2]), "+f"(c[3])
        : "r"(a[0]), "r"(a[1]), "r"(a[2]), "r"(a[3]), "r"(b0), "r"(b1));
}

// Bit-exact reference distance: sequential-k FMA chain of x*(2w), then
// dist = fl( fl(xn - dot2) + wn ).  (matches R3-passing semantics)
__device__ __forceinline__ float dist_exact(const float* __restrict__ xr,
                                            const float* __restrict__ w,
                                            float xn, float wnj) {
    float acc = 0.f;
    #pragma unroll
    for (int k4 = 0; k4 < 16; k4++) {
        float4 wv = __ldg((const float4*)w + k4);
        acc = __fmaf_rn(xr[4 * k4 + 0], 2.f * wv.x, acc);
        acc = __fmaf_rn(xr[4 * k4 + 1], 2.f * wv.y, acc);
        acc = __fmaf_rn(xr[4 * k4 + 2], 2.f * wv.z, acc);
        acc = __fmaf_rn(xr[4 * k4 + 3], 2.f * wv.w, acc);
    }
    return __fadd_rn(__fsub_rn(xn, acc), wnj);
}

// ---------------------------------------------------------------------------
// k_prep: wnorm exact (reference order); B -> bf16(2w); seed EMA; zero diff
// ---------------------------------------------------------------------------
__global__ void k_prep(const float* __restrict__ embed,
                       const float* __restrict__ cluster,
                       const float* __restrict__ eavg,
                       float* __restrict__ out) {
    int t = blockIdx.x * blockDim.x + threadIdx.x;   // 65536
    out[OFF_NEA + t] = 0.99f * eavg[t];
    g_Bbf16[t] = __float2bfloat16_rn(2.f * embed[t]);
    if (t < K_CODE) {
        out[OFF_NCS + t] = 0.99f * cluster[t];
        const float* w = embed + (size_t)t * E_DIM;
        float s = 0.f;
        #pragma unroll
        for (int i = 0; i < E_DIM; i++)
            s = __fadd_rn(s, __fmul_rn(w[i], w[i]));
        g_wnorm[t] = s;
    }
    if (t == 0) g_diff_acc = 0.0;
}

// ---------------------------------------------------------------------------
// k_mma: bf16 mma.sync filter + exact fp32 verify + fused epilogue
// ---------------------------------------------------------------------------
__global__ void __launch_bounds__(256, 1)
k_mma(const float* __restrict__ z_e, const float* __restrict__ embed,
      float* __restrict__ out) {
    extern __shared__ char smem[];
    uint32_t* Bs  = (uint32_t*)(smem + SM_B);     // [code][36 words]
    float*    Xs  = (float*)(smem + SM_X);        // [256][68]
    float*    wns = (float*)(smem + SM_WN);
    int*      fin = (int*)(smem + SM_FIN);
    float*    dsum = (float*)(smem + SM_DSUM);

    const int tid  = threadIdx.x;                 // 256
    const int wid  = tid >> 5;                    // 8 warps
    const int lane = tid & 31;
    const int g    = lane >> 2;                   // 0..7  (mma col group)
    const int t4   = lane & 3;                    // 0..3
    const int tbase = blockIdx.x * MT;

    // ---- stage B (8192 uint4), wnorm, X tile ----
    {
        const uint4* src = (const uint4*)g_Bbf16;
        for (int i = tid; i < 8192; i += 256) {
            int n = i >> 3, w4 = (i & 7) << 2;
            *(uint4*)(Bs + n * 36 + w4) = src[i];
        }
    }
    for (int i = tid; i < K_CODE; i += 256) wns[i] = g_wnorm[i];
    for (int i = tid; i < MT * 16; i += 256) {
        int r = i >> 4, c4 = (i & 15) << 2;
        float4 x = *(const float4*)(z_e + (size_t)(tbase + r) * E_DIM + c4);
        *(float4*)(Xs + r * 68 + c4) = x;
    }
    __syncthreads();

    // ---- A fragments (bf16) from Xs: 2 m-tiles x 4 k-steps x 4 regs ----
    uint32_t A[2][4][4];
    #pragma unroll
    for (int mt = 0; mt < 2; mt++)
        #pragma unroll
        for (int q = 0; q < 2; q++) {
            int tl = wid * 32 + (lane >> 2) + mt * 16 + q * 8;
            const float* xr = Xs + tl * 68;
            #pragma unroll
            for (int ks = 0; ks < 4; ks++)
                #pragma unroll
                for (int kh = 0; kh < 2; kh++) {
                    int kk = 2 * (t4 + 4 * kh + 8 * ks);
                    float2 v = *(const float2*)(xr + kk);
                    __nv_bfloat162 h = __floats2bfloat162_rn(v.x, v.y);
                    A[mt][ks][q + 2 * kh] = *(uint32_t*)&h;
                }
        }

    // ---- filter loop: all 1024 codes, running min + candidate superset ----
    float rm[4] = {FLT_MAX, FLT_MAX, FLT_MAX, FLT_MAX};
    int   cnt[4] = {0, 0, 0, 0};
    int   arr[4][NCAND];

    const uint32_t* bp = Bs + g * 36 + t4;

    #pragma unroll 1
    for (int nt = 0; nt < NTILES; nt++) {
        const uint32_t* bb = bp + nt * 288;      // 8 codes * 36 words
        float c0[4] = {0.f, 0.f, 0.f, 0.f};
        float c1[4] = {0.f, 0.f, 0.f, 0.f};
        #pragma unroll
        for (int ks = 0; ks < 4; ks++) {
            uint32_t b0 = bb[8 * ks];
            uint32_t b1 = bb[8 * ks + 4];
            mma16816(c0, A[0][ks], b0, b1);
            mma16816(c1, A[1][ks], b0, b1);
        }
        int   j0  = nt * 8 + 2 * t4;
        float wn0 = wns[j0], wn1 = wns[j0 + 1];

        #define UPD(q, s, j)                                             \
            do { float _s = (s);                                         \
                 if (_s < rm[q]) rm[q] = _s;                             \
                 if (_s <= rm[q] + TAU) {                                \
                     if (cnt[q] < NCAND) arr[q][cnt[q]] = (j);           \
                     cnt[q]++; } } while (0)

        UPD(0, wn0 - c0[0], j0); UPD(0, wn1 - c0[1], j0 + 1);
        UPD(1, wn0 - c0[2], j0); UPD(1, wn1 - c0[3], j0 + 1);
        UPD(2, wn0 - c1[0], j0); UPD(2, wn1 - c1[1], j0 + 1);
        UPD(3, wn0 - c1[2], j0); UPD(3, wn1 - c1[3], j0 + 1);
        #undef UPD
    }

    // ---- exact resolution per token row, quad merge ----
    #pragma unroll
    for (int q = 0; q < 4; q++) {
        int tl = wid * 32 + (lane >> 2) + (q >> 1) * 16 + (q & 1) * 8;
        const float* xr = Xs + tl * 68;
        float xn = 0.f;
        #pragma unroll
        for (int k = 0; k < E_DIM; k++)
            xn = __fadd_rn(xn, __fmul_rn(xr[k], xr[k]));

        float bd = FLT_MAX;
        int   bi = 0x7FFFFFFF;
        if (cnt[q] > NCAND) {
            // rare overflow: exact scan of this thread's own 256 columns
            for (int nt = 0; nt < NTILES; nt++) {
                int j = nt * 8 + 2 * t4;
                float d0 = dist_exact(xr, embed + (size_t)j * E_DIM, xn, wns[j]);
                if (d0 < bd) { bd = d0; bi = j; }
                float d1 = dist_exact(xr, embed + (size_t)(j + 1) * E_DIM, xn, wns[j + 1]);
                if (d1 < bd) { bd = d1; bi = j + 1; }
            }
        } else {
            for (int i = 0; i < cnt[q]; i++) {       // ascending j
                int j = arr[q][i];
                float d = dist_exact(xr, embed + (size_t)j * E_DIM, xn, wns[j]);
                if (d < bd) { bd = d; bi = j; }
            }
        }
        // merge across the 4 lanes of the quad (lowest dist, then lowest idx)
        #pragma unroll
        for (int off = 1; off < 4; off <<= 1) {
            float ob = __shfl_xor_sync(0xffffffffu, bd, off);
            int   oi = __shfl_xor_sync(0xffffffffu, bi, off);
            if (ob < bd || (ob == bd && oi < bi)) { bd = ob; bi = oi; }
        }
        if (t4 == 0) {
            fin[tl] = bi;
            out[OFF_IND + tbase + tl] = (float)bi;
            atomicAdd(out + OFF_NCS + bi, 0.01f);
        }
    }
    __syncthreads();

    // ---- fused epilogue: z_q_st + diff + EMA scatter (coalesced) ----
    float ldiff = 0.f;
    for (int i = tid; i < MT * E_DIM; i += 256) {
        int row = i >> 6, col = i & 63;
        int idx = fin[row];
        float z = Xs[row * 68 + col];
        float w = __ldg(embed + (size_t)idx * E_DIM + col);
        float d = __fsub_rn(w, z);
        ldiff += d * d;
        out[OFF_ZQ + (size_t)(tbase + row) * E_DIM + col] = __fadd_rn(z, d);
        atomicAdd(out + OFF_NEA + (size_t)idx * E_DIM + col, 0.01f * z);
    }
    #pragma unroll
    for (int o = 16; o > 0; o >>= 1)
        ldiff += __shfl_down_sync(0xffffffffu, ldiff, o);
    if (lane == 0) dsum[wid] = ldiff;
    __syncthreads();
    if (tid == 0) {
        double s = 0.0;
        #pragma unroll
        for (int i = 0; i < 8; i++) s += (double)dsum[i];
        atomicAdd(&g_diff_acc, s);
    }
}

// ---------------------------------------------------------------------------
// k_final: n = sum(new_cluster_size); cs normalize; new_embed; diff
// ---------------------------------------------------------------------------
__global__ void k_final(float* __restrict__ out) {
    __shared__ float red[1024];
    int k = threadIdx.x;
    float c = out[OFF_NCS + k];
    red[k] = c;
    __syncthreads();
    for (int o = 512; o > 0; o >>= 1) {
        if (k < o) red[k] += red[k + o];
        __syncthreads();
    }
    float n = red[0];
    float cs = (c + 1e-5f) / (n + 1024.0f * 1e-5f) * n;
    const float* src = out + OFF_NEA  + (size_t)k * E_DIM;
    float*       dst = out + OFF_NEMB + (size_t)k * E_DIM;
    #pragma unroll
    for (int u = 0; u < E_DIM; u++) dst[u] = src[u] / cs;
    if (k == 0) out[OFF_DIFF] = (float)(g_diff_acc * (1.0 / 4194304.0));
}

// ---------------------------------------------------------------------------
extern "C" void kernel_launch(void* const* d_in, const int* in_sizes, int n_in,
                              void* d_out, int out_size) {
    const float* z_e     = (const float*)d_in[0];
    const float* embed   = (const float*)d_in[1];
    const float* cluster = (const float*)d_in[2];
    const float* eavg    = (const float*)d_in[3];
    float* out = (float*)d_out;

    int T = in_sizes[0] / E_DIM;     // 65536 tokens

    static int configured = 0;
    if (!configured) {
        cudaFuncSetAttribute(k_mma, cudaFuncAttributeMaxDynamicSharedMemorySize,
                             SM_TOTAL);
        configured = 1;
    }

    k_prep<<<512, 128>>>(embed, cluster, eavg, out);
    k_mma<<<T / MT, 256, SM_TOTAL>>>(z_e, embed, out);
    k_final<<<1, 1024>>>(out);
}

// round 7
// speedup vs baseline: 8.5062x; 8.5062x over previous
#include <cuda_runtime.h>
#include <cuda_bf16.h>
#include <cfloat>
#include <cstdint>

#define E_DIM   64
#define K_CODE  1024
#define MT      256           // tokens per block
#define NTILES  128           // 1024 codes / 8 per mma tile
#define TAU     2e-3f

// Output layout (float32, tuple order)
#define OFF_ZQ   0
#define OFF_DIFF 4194304
#define OFF_IND  4194305
#define OFF_NEMB 4259841
#define OFF_NCS  4325377
#define OFF_NEA  4326401

// smem layout (byte offsets)
#define SM_B     0            // 1024 codes x 36 words (bf16(2w) padded)  147456 B
#define SM_X     147456       // 256 x 68 fp32                             69632 B
#define SM_WN    217088       // 1024 fp32                                  4096 B
#define SM_FIN   221184       // 256 int                                    1024 B
#define SM_DSUM  222208       // 8 fp32                                       32 B
#define SM_TOTAL 222240

__device__ float         g_wnorm[K_CODE];
__device__ double        g_diff_acc;
__device__ __nv_bfloat16 g_Bbf16[K_CODE * E_DIM];   // bf16(2*w), k-contiguous

__device__ __forceinline__ void mma16816(float* c, const uint32_t* a,
                                         uint32_t b0, uint32_t b1) {
    asm volatile(
        "mma.sync.aligned.m16n8k16.row.col.f32.bf16.bf16.f32 "
        "{%0,%1,%2,%3}, {%4,%5,%6,%7}, {%8,%9}, {%0,%1,%2,%3};"
        : "+f"(c[0]), "+f"(c[1]), "+f"(c[2]), "+f"(c[3])
        : "r"(a[0]), "r"(a[1]), "r"(a[2]), "r"(a[3]), "r"(b0), "r"(b1));
}

// Bit-exact reference distance (kept OUT of the hot loop's I-footprint).
// dot2 = sequential-k FMA chain of x*(2w); dist = fl( fl(xn - dot2) + wn ).
__device__ __noinline__ float dist_exact(const float* __restrict__ xr,
                                         const float* __restrict__ w,
                                         float xn, float wnj) {
    float acc = 0.f;
    #pragma unroll
    for (int k4 = 0; k4 < 16; k4++) {
        float4 wv = __ldg((const float4*)w + k4);
        acc = __fmaf_rn(xr[4 * k4 + 0], 2.f * wv.x, acc);
        acc = __fmaf_rn(xr[4 * k4 + 1], 2.f * wv.y, acc);
        acc = __fmaf_rn(xr[4 * k4 + 2], 2.f * wv.z, acc);
        acc = __fmaf_rn(xr[4 * k4 + 3], 2.f * wv.w, acc);
    }
    return __fadd_rn(__fsub_rn(xn, acc), wnj);
}

// ---------------------------------------------------------------------------
// k_prep: wnorm exact (reference order); B -> bf16(2w); seed EMA; zero diff
// ---------------------------------------------------------------------------
__global__ void k_prep(const float* __restrict__ embed,
                       const float* __restrict__ cluster,
                       const float* __restrict__ eavg,
                       float* __restrict__ out) {
    int t = blockIdx.x * blockDim.x + threadIdx.x;   // 65536
    out[OFF_NEA + t] = 0.99f * eavg[t];
    g_Bbf16[t] = __float2bfloat16_rn(2.f * embed[t]);
    if (t < K_CODE) {
        out[OFF_NCS + t] = 0.99f * cluster[t];
        const float* w = embed + (size_t)t * E_DIM;
        float s = 0.f;
        #pragma unroll
        for (int i = 0; i < E_DIM; i++)
            s = __fadd_rn(s, __fmul_rn(w[i], w[i]));
        g_wnorm[t] = s;
    }
    if (t == 0) g_diff_acc = 0.0;
}

// ---------------------------------------------------------------------------
// k_mma: two-pass bf16 mma.sync filter + inline exact fp32 verify
// ---------------------------------------------------------------------------
__global__ void __launch_bounds__(256, 1)
k_mma(const float* __restrict__ z_e, const float* __restrict__ embed,
      float* __restrict__ out) {
    extern __shared__ char smem[];
    uint32_t* Bs   = (uint32_t*)(smem + SM_B);     // [code][36 words]
    float*    Xs   = (float*)(smem + SM_X);        // [256][68]
    float*    wns  = (float*)(smem + SM_WN);
    int*      fin  = (int*)(smem + SM_FIN);
    float*    dsum = (float*)(smem + SM_DSUM);

    const int tid  = threadIdx.x;                  // 256
    const int wid  = tid >> 5;                     // 8 warps
    const int lane = tid & 31;
    const int g    = lane >> 2;                    // 0..7
    const int t4   = lane & 3;                     // 0..3
    const int tbase = blockIdx.x * MT;

    // ---- stage B (8192 uint4), wnorm, X tile ----
    {
        const uint4* src = (const uint4*)g_Bbf16;
        for (int i = tid; i < 8192; i += 256) {
            int n = i >> 3, w4 = (i & 7) << 2;
            *(uint4*)(Bs + n * 36 + w4) = src[i];
        }
    }
    for (int i = tid; i < K_CODE; i += 256) wns[i] = g_wnorm[i];
    for (int i = tid; i < MT * 16; i += 256) {
        int r = i >> 4, c4 = (i & 15) << 2;
        float4 x = *(const float4*)(z_e + (size_t)(tbase + r) * E_DIM + c4);
        *(float4*)(Xs + r * 68 + c4) = x;
    }
    __syncthreads();

    // ---- A fragments (bf16) from Xs: 2 m-tiles x 4 k-steps x 4 regs ----
    uint32_t A[2][4][4];
    const float* xrp[4];
    #pragma unroll
    for (int mt = 0; mt < 2; mt++)
        #pragma unroll
        for (int q = 0; q < 2; q++) {
            int tl = wid * 32 + (lane >> 2) + mt * 16 + q * 8;
            const float* xr = Xs + tl * 68;
            xrp[q + 2 * mt] = xr;     // order: [q0m0, q1m0, q0m1, q1m1]
            #pragma unroll
            for (int ks = 0; ks < 4; ks++)
                #pragma unroll
                for (int kh = 0; kh < 2; kh++) {
                    int kk = 2 * (t4 + 4 * kh + 8 * ks);
                    float2 v = *(const float2*)(xr + kk);
                    __nv_bfloat162 h = __floats2bfloat162_rn(v.x, v.y);
                    A[mt][ks][q + 2 * kh] = *(uint32_t*)&h;
                }
        }
    // accumulator slot -> xrp mapping: c0[0,1]=row q0m0, c0[2,3]=q1m0,
    //                                  c1[0,1]=q0m1,     c1[2,3]=q1m1

    // ---- PASS 1: running min only (branch-free) ----
    float rm[4] = {FLT_MAX, FLT_MAX, FLT_MAX, FLT_MAX};
    const uint32_t* bp = Bs + g * 36 + t4;

    #pragma unroll 1
    for (int nt = 0; nt < NTILES; nt++) {
        const uint32_t* bb = bp + nt * 288;
        float c0[4] = {0.f, 0.f, 0.f, 0.f};
        float c1[4] = {0.f, 0.f, 0.f, 0.f};
        #pragma unroll
        for (int ks = 0; ks < 4; ks++) {
            uint32_t b0 = bb[8 * ks];
            uint32_t b1 = bb[8 * ks + 4];
            mma16816(c0, A[0][ks], b0, b1);
            mma16816(c1, A[1][ks], b0, b1);
        }
        int   j0  = nt * 8 + 2 * t4;
        float wn0 = wns[j0], wn1 = wns[j0 + 1];
        rm[0] = fminf(rm[0], fminf(wn0 - c0[0], wn1 - c0[1]));
        rm[1] = fminf(rm[1], fminf(wn0 - c0[2], wn1 - c0[3]));
        rm[2] = fminf(rm[2], fminf(wn0 - c1[0], wn1 - c1[1]));
        rm[3] = fminf(rm[3], fminf(wn0 - c1[2], wn1 - c1[3]));
    }

    // quad-reduce -> per-token approx min, threshold = min + TAU
    float th[4];
    #pragma unroll
    for (int q = 0; q < 4; q++) {
        float v = rm[q];
        v = fminf(v, __shfl_xor_sync(0xffffffffu, v, 1));
        v = fminf(v, __shfl_xor_sync(0xffffffffu, v, 2));
        th[q] = v + TAU;
    }

    // per-token exact xnorm (reference order)
    float xnv[4];
    #pragma unroll
    for (int q = 0; q < 4; q++) {
        const float* xr = xrp[q];
        float s = 0.f;
        #pragma unroll
        for (int k = 0; k < E_DIM; k++)
            s = __fadd_rn(s, __fmul_rn(xr[k], xr[k]));
        xnv[q] = s;
    }

    // ---- PASS 2: rescan; s <= th -> inline exact eval (rare) ----
    float bd[4] = {FLT_MAX, FLT_MAX, FLT_MAX, FLT_MAX};
    int   bi[4] = {0x7FFFFFFF, 0x7FFFFFFF, 0x7FFFFFFF, 0x7FFFFFFF};

    #pragma unroll 1
    for (int nt = 0; nt < NTILES; nt++) {
        const uint32_t* bb = bp + nt * 288;
        float c0[4] = {0.f, 0.f, 0.f, 0.f};
        float c1[4] = {0.f, 0.f, 0.f, 0.f};
        #pragma unroll
        for (int ks = 0; ks < 4; ks++) {
            uint32_t b0 = bb[8 * ks];
            uint32_t b1 = bb[8 * ks + 4];
            mma16816(c0, A[0][ks], b0, b1);
            mma16816(c1, A[1][ks], b0, b1);
        }
        int   j0  = nt * 8 + 2 * t4;
        float wn0 = wns[j0], wn1 = wns[j0 + 1];

        // candidates arrive in ascending j per (thread,q): strict '<' on the
        // exact dist keeps the lowest index on exact fp32 ties.
        #define CHK(q, s, j, wnj)                                             \
            do { if ((s) <= th[q]) {                                          \
                     float _d = dist_exact(xrp[q],                            \
                                           embed + (size_t)(j) * E_DIM,       \
                                           xnv[q], (wnj));                    \
                     if (_d < bd[q]) { bd[q] = _d; bi[q] = (j); } } } while (0)

        CHK(0, wn0 - c0[0], j0, wn0); CHK(0, wn1 - c0[1], j0 + 1, wn1);
        CHK(1, wn0 - c0[2], j0, wn0); CHK(1, wn1 - c0[3], j0 + 1, wn1);
        CHK(2, wn0 - c1[0], j0, wn0); CHK(2, wn1 - c1[1], j0 + 1, wn1);
        CHK(3, wn0 - c1[2], j0, wn0); CHK(3, wn1 - c1[3], j0 + 1, wn1);
        #undef CHK
    }

    // ---- quad merge (lowest dist, then lowest index) + store ----
    #pragma unroll
    for (int q = 0; q < 4; q++) {
        float d = bd[q]; int j = bi[q];
        #pragma unroll
        for (int off = 1; off < 4; off <<= 1) {
            float od = __shfl_xor_sync(0xffffffffu, d, off);
            int   oj = __shfl_xor_sync(0xffffffffu, j, off);
            if (od < d || (od == d && oj < j)) { d = od; j = oj; }
        }
        if (t4 == 0) {
            int tl = wid * 32 + (lane >> 2) + (q >> 1) * 16 + (q & 1) * 8;
            fin[tl] = j;
            out[OFF_IND + tbase + tl] = (float)j;
            atomicAdd(out + OFF_NCS + j, 0.01f);
        }
    }
    __syncthreads();

    // ---- fused epilogue: z_q_st + diff + EMA scatter (coalesced) ----
    float ldiff = 0.f;
    for (int i = tid; i < MT * E_DIM; i += 256) {
        int row = i >> 6, col = i & 63;
        int idx = fin[row];
        float z = Xs[row * 68 + col];
        float w = __ldg(embed + (size_t)idx * E_DIM + col);
        float d = __fsub_rn(w, z);
        ldiff += d * d;
        out[OFF_ZQ + (size_t)(tbase + row) * E_DIM + col] = __fadd_rn(z, d);
        atomicAdd(out + OFF_NEA + (size_t)idx * E_DIM + col, 0.01f * z);
    }
    #pragma unroll
    for (int o = 16; o > 0; o >>= 1)
        ldiff += __shfl_down_sync(0xffffffffu, ldiff, o);
    if (lane == 0) dsum[wid] = ldiff;
    __syncthreads();
    if (tid == 0) {
        double s = 0.0;
        #pragma unroll
        for (int i = 0; i < 8; i++) s += (double)dsum[i];
        atomicAdd(&g_diff_acc, s);
    }
}

// ---------------------------------------------------------------------------
// k_final: n = sum(new_cluster_size); cs normalize; new_embed; diff
// ---------------------------------------------------------------------------
__global__ void k_final(float* __restrict__ out) {
    __shared__ float red[1024];
    int k = threadIdx.x;
    float c = out[OFF_NCS + k];
    red[k] = c;
    __syncthreads();
    for (int o = 512; o > 0; o >>= 1) {
        if (k < o) red[k] += red[k + o];
        __syncthreads();
    }
    float n = red[0];
    float cs = (c + 1e-5f) / (n + 1024.0f * 1e-5f) * n;
    const float* src = out + OFF_NEA  + (size_t)k * E_DIM;
    float*       dst = out + OFF_NEMB + (size_t)k * E_DIM;
    #pragma unroll
    for (int u = 0; u < E_DIM; u++) dst[u] = src[u] / cs;
    if (k == 0) out[OFF_DIFF] = (float)(g_diff_acc * (1.0 / 4194304.0));
}

// ---------------------------------------------------------------------------
extern "C" void kernel_launch(void* const* d_in, const int* in_sizes, int n_in,
                              void* d_out, int out_size) {
    const float* z_e     = (const float*)d_in[0];
    const float* embed   = (const float*)d_in[1];
    const float* cluster = (const float*)d_in[2];
    const float* eavg    = (const float*)d_in[3];
    float* out = (float*)d_out;

    int T = in_sizes[0] / E_DIM;     // 65536 tokens

    static int configured = 0;
    if (!configured) {
        cudaFuncSetAttribute(k_mma, cudaFuncAttributeMaxDynamicSharedMemorySize,
                             SM_TOTAL);
        configured = 1;
    }

    k_prep<<<512, 128>>>(embed, cluster, eavg, out);
    k_mma<<<T / MT, 256, SM_TOTAL>>>(z_e, embed, out);
    k_final<<<1, 1024>>>(out);
}